// round 14
// baseline (speedup 1.0000x reference)
#include <cuda_runtime.h>
#include <cuda_fp16.h>
#include <cstdint>
#include <cstddef>

typedef __half h16;

#define BDIM 16384
#define D1   1536
#define D2   3072
#define DH   512
#define DOUT 6

// ---------------- scratch (static device memory; no allocations) ----------------
static constexpr size_t SZ_X   = (size_t)BDIM * D1;
static constexpr size_t SZ_H   = (size_t)BDIM * DH;
static constexpr size_t SZ_WGE = (size_t)D1 * D1;
static constexpr size_t SZ_WGI = (size_t)D2 * D1;
static constexpr size_t SZ_W1  = (size_t)D1 * DH;
static constexpr size_t SZ_W2  = (size_t)DH * DH;

static constexpr size_t O_X   = 0;
static constexpr size_t O_GE  = O_X  + SZ_X;
static constexpr size_t O_GI  = O_GE + SZ_X;
static constexpr size_t O_H1  = O_GI + SZ_X;
static constexpr size_t O_H2  = O_H1 + SZ_H;
static constexpr size_t O_WGE = O_H2 + SZ_H;
static constexpr size_t O_WGI = O_WGE + SZ_WGE;
static constexpr size_t O_W1  = O_WGI + SZ_WGI;
static constexpr size_t O_W2  = O_W1 + SZ_W1;
static constexpr size_t SCRATCH_TOTAL = O_W2 + SZ_W2;

__device__ __align__(1024) h16 g_scratch[SCRATCH_TOTAL];

// ---------------- ptx helpers ----------------
__device__ __forceinline__ uint32_t smem_u32(const void* p) {
    uint32_t a;
    asm("{ .reg .u64 t; cvta.to.shared.u64 t, %1; cvt.u32.u64 %0, t; }" : "=r"(a) : "l"(p));
    return a;
}

__device__ __forceinline__ void cp16(uint32_t dst, const void* src) {
    asm volatile("cp.async.cg.shared.global [%0], [%1], 16;" :: "r"(dst), "l"(src) : "memory");
}

__device__ __forceinline__ void ldmx4(uint32_t* r, uint32_t addr) {
    asm volatile("ldmatrix.sync.aligned.m8n8.x4.shared.b16 {%0,%1,%2,%3}, [%4];"
        : "=r"(r[0]), "=r"(r[1]), "=r"(r[2]), "=r"(r[3]) : "r"(addr));
}

__device__ __forceinline__ void mma16816(float* c, const uint32_t* a, const uint32_t* b) {
    asm volatile(
        "mma.sync.aligned.m16n8k16.row.col.f32.f16.f16.f32 "
        "{%0,%1,%2,%3},{%4,%5,%6,%7},{%8,%9},{%0,%1,%2,%3};\n"
        : "+f"(c[0]), "+f"(c[1]), "+f"(c[2]), "+f"(c[3])
        : "r"(a[0]), "r"(a[1]), "r"(a[2]), "r"(a[3]),
          "r"(b[0]), "r"(b[1]));
}

// ---------------- prep kernels ----------------
__global__ void cvt_kernel4(const float4* __restrict__ src,
                            __half2* __restrict__ dst, size_t n4) {
    size_t stride = (size_t)gridDim.x * blockDim.x;
    for (size_t i = (size_t)blockIdx.x * blockDim.x + threadIdx.x; i < n4; i += stride) {
        float4 v = src[i];
        dst[2 * i]     = __floats2half2_rn(v.x, v.y);
        dst[2 * i + 1] = __floats2half2_rn(v.z, v.w);
    }
}

template<bool MASKED>
__global__ void prep_T(const float* __restrict__ w, const float* __restrict__ mask,
                       h16* __restrict__ t, int Kd, int Nd) {
    __shared__ float tl[32][33];
    const int k0 = blockIdx.x * 32, n0 = blockIdx.y * 32;
    const int tx = threadIdx.x, ty = threadIdx.y;  // 32 x 8
#pragma unroll
    for (int i = 0; i < 32; i += 8)
        tl[ty + i][tx] = w[(size_t)(k0 + ty + i) * Nd + (n0 + tx)];
    __syncthreads();
#pragma unroll
    for (int i = 0; i < 32; i += 8) {
        const int n = n0 + ty + i, k = k0 + tx;
        float v = tl[tx][ty + i];
        const size_t idx = (size_t)n * Kd + k;
        if (MASKED) v *= mask[idx];
        t[idx] = __float2half_rn(v);
    }
}

// ---------------- mma.sync GEMM: C = A * B^T(+concat) + bias (opt relu), fp16 ----------------
// BK=64 (128B swizzled rows), 3-stage cp.async (1 barrier/stage), 2 CTAs/SM.
// Warp tile 64x32. Big config: CTA 128x96, 192 thr (reg cap 170 -> frag double-buffer).
// Small config: CTA 128x128, 256 thr, single-buffer frags (reg cap 128).
template<int CBM, int CBN, int THREADS, bool DBUF, bool RELU, bool CONCAT>
__global__ __launch_bounds__(THREADS, 2)
void gemm_hmma(const h16* __restrict__ A, const h16* __restrict__ A2,
               int ksplit,
               const h16* __restrict__ Bt,  // [N][K]
               const float* __restrict__ bias,
               h16* __restrict__ O,
               int N, int K)
{
    constexpr int WARPS_N = CBN / 32;
    constexpr int NI = 4;    // 64/16 M-frags
    constexpr int NJ = 4;    // 32/8  N-frags
    constexpr int NJP = 2;   // 32/16 N-frag pairs
    constexpr int ABYTES = CBM * 128;
    constexpr int BBYTES = CBN * 128;
    constexpr int STAGEB = ABYTES + BBYTES;
    constexpr int ACH = CBM * 8;
    constexpr int BCH = CBN * 8;

    extern __shared__ __align__(1024) char smem[];
    const uint32_t sb = smem_u32(smem);

    const int tid  = threadIdx.x;
    const int lane = tid & 31;
    const int warp = tid >> 5;
    const int wm = warp / WARPS_N;
    const int wn = warp % WARPS_N;
    const int blockN = blockIdx.x * CBN;
    const int blockM = blockIdx.y * CBM;

    // ldmatrix lane decomposition
    const int q = lane >> 3;
    const int m8 = lane & 7;
    const int qrA = q & 1;
    const int qcA = q >> 1;
    const int qrB = q >> 1;
    const int qcB = q & 1;

    uint32_t rA[NI], xA[NI];
#pragma unroll
    for (int i = 0; i < NI; i++) {
        int row = wm * 64 + i * 16 + qrA * 8 + m8;
        rA[i] = (uint32_t)row * 128u;
        xA[i] = (uint32_t)(row & 7);
    }
    uint32_t rB[NJP], xB[NJP];
#pragma unroll
    for (int jp = 0; jp < NJP; jp++) {
        int row = wn * 32 + jp * 16 + qrB * 8 + m8;
        rB[jp] = (uint32_t)row * 128u;
        xB[jp] = (uint32_t)(row & 7);
    }

    float acc[NI][NJ][4];
#pragma unroll
    for (int i = 0; i < NI; i++)
#pragma unroll
        for (int j = 0; j < NJ; j++)
#pragma unroll
            for (int r = 0; r < 4; r++) acc[i][j][r] = 0.f;

    const int S = K / 64;

    auto do_load = [&](int s) {
        const int k0 = s * 64;
        const h16* a;
        size_t lda;
        if (CONCAT && k0 >= ksplit) {
            lda = (size_t)(K - ksplit);
            a = A2 + (size_t)blockM * lda + (k0 - ksplit);
        } else {
            lda = CONCAT ? (size_t)ksplit : (size_t)K;
            a = A + (size_t)blockM * lda + k0;
        }
        const h16* b = Bt + (size_t)blockN * K + k0;
        const uint32_t buf = sb + (uint32_t)(s % 3) * STAGEB;
#pragma unroll 1
        for (int c = tid; c < ACH; c += THREADS) {
            const int row = c >> 3;
            const int col = c & 7;
            const uint32_t soff = (uint32_t)row * 128u + (uint32_t)((col ^ (row & 7)) * 16);
            cp16(buf + soff, (const char*)(a + (size_t)row * lda) + col * 16);
        }
#pragma unroll 1
        for (int c = tid; c < BCH; c += THREADS) {
            const int row = c >> 3;
            const int col = c & 7;
            const uint32_t soff = (uint32_t)row * 128u + (uint32_t)((col ^ (row & 7)) * 16);
            cp16(buf + ABYTES + soff, (const char*)(b + (size_t)row * K) + col * 16);
        }
    };

    do_load(0);
    asm volatile("cp.async.commit_group;" ::: "memory");
    if (S > 1) {
        do_load(1);
        asm volatile("cp.async.commit_group;" ::: "memory");
    }

    for (int s = 0; s < S; s++) {
        if (s < S - 1) asm volatile("cp.async.wait_group 1;" ::: "memory");
        else           asm volatile("cp.async.wait_group 0;" ::: "memory");
        __syncthreads();   // single barrier per stage (3-stage ring)

        if (s + 2 < S) {
            do_load(s + 2);
            asm volatile("cp.async.commit_group;" ::: "memory");
        }

        const uint32_t buf = sb + (uint32_t)(s % 3) * STAGEB;
        const uint32_t bA = buf;
        const uint32_t bB = buf + ABYTES;

        if (DBUF) {
            // explicit fragment double-buffering: prefetch ks+1 under ks MMAs
            uint32_t af[2][NI][4], bf[2][NJP][4];
            {
                const uint32_t cA = (uint32_t)qcA, cB = (uint32_t)qcB;
#pragma unroll
                for (int i = 0; i < NI; i++)
                    ldmx4(af[0][i], bA + rA[i] + ((cA ^ xA[i]) << 4));
#pragma unroll
                for (int jp = 0; jp < NJP; jp++)
                    ldmx4(bf[0][jp], bB + rB[jp] + ((cB ^ xB[jp]) << 4));
            }
#pragma unroll
            for (int ks = 0; ks < 4; ks++) {
                const int cur = ks & 1, nxt = cur ^ 1;
                if (ks < 3) {
                    const uint32_t cA = (uint32_t)((ks + 1) * 2 + qcA);
                    const uint32_t cB = (uint32_t)((ks + 1) * 2 + qcB);
#pragma unroll
                    for (int i = 0; i < NI; i++)
                        ldmx4(af[nxt][i], bA + rA[i] + ((cA ^ xA[i]) << 4));
#pragma unroll
                    for (int jp = 0; jp < NJP; jp++)
                        ldmx4(bf[nxt][jp], bB + rB[jp] + ((cB ^ xB[jp]) << 4));
                }
#pragma unroll
                for (int j = 0; j < NJ; j++)
#pragma unroll
                    for (int i = 0; i < NI; i++)
                        mma16816(acc[i][j], af[cur][i], &bf[cur][j >> 1][(j & 1) * 2]);
            }
        } else {
#pragma unroll
            for (int ks = 0; ks < 4; ks++) {
                const uint32_t cA = (uint32_t)(ks * 2 + qcA);
                const uint32_t cB = (uint32_t)(ks * 2 + qcB);
                uint32_t af[NI][4], bf[NJP][4];
#pragma unroll
                for (int i = 0; i < NI; i++)
                    ldmx4(af[i], bA + rA[i] + ((cA ^ xA[i]) << 4));
#pragma unroll
                for (int jp = 0; jp < NJP; jp++)
                    ldmx4(bf[jp], bB + rB[jp] + ((cB ^ xB[jp]) << 4));
#pragma unroll
                for (int j = 0; j < NJ; j++)
#pragma unroll
                    for (int i = 0; i < NI; i++)
                        mma16816(acc[i][j], af[i], &bf[j >> 1][(j & 1) * 2]);
            }
        }
    }

    // ---- epilogue: bias, optional relu, fp16 store
    const int g  = lane >> 2;
    const int tg = lane & 3;
#pragma unroll
    for (int i = 0; i < NI; i++) {
#pragma unroll
        for (int j = 0; j < NJ; j++) {
            int row0 = blockM + wm * 64 + i * 16 + g;
            int col  = blockN + wn * 32 + j * 8 + tg * 2;
            float b0 = bias[col], b1 = bias[col + 1];
#pragma unroll
            for (int h = 0; h < 2; h++) {
                int row = row0 + h * 8;
                float v0 = acc[i][j][h * 2 + 0] + b0;
                float v1 = acc[i][j][h * 2 + 1] + b1;
                if (RELU) { v0 = fmaxf(v0, 0.f); v1 = fmaxf(v1, 0.f); }
                *(__half2*)&O[(size_t)row * N + col] = __floats2half2_rn(v0, v1);
            }
        }
    }
}

// ---------------- final layer: [B,512] x [512,6] + bias, relu (fp32) ----------------
__global__ void final_kernel(const h16* __restrict__ hh,
                             const float* __restrict__ w3, const float* __restrict__ b3,
                             float* __restrict__ out)
{
    int warpId = (int)((blockIdx.x * (size_t)blockDim.x + threadIdx.x) >> 5);
    int lane = threadIdx.x & 31;
    if (warpId >= BDIM) return;
    const h16* ph = hh + (size_t)warpId * DH;
    float acc[6] = {0.f, 0.f, 0.f, 0.f, 0.f, 0.f};
    for (int k = lane; k < DH; k += 32) {
        float h = __half2float(ph[k]);
#pragma unroll
        for (int n = 0; n < 6; n++) acc[n] += h * w3[k * 6 + n];
    }
#pragma unroll
    for (int n = 0; n < 6; n++)
#pragma unroll
        for (int off = 16; off; off >>= 1)
            acc[n] += __shfl_xor_sync(0xffffffffu, acc[n], off);
    if (lane == 0) {
#pragma unroll
        for (int n = 0; n < 6; n++)
            out[(size_t)warpId * 6 + n] = fmaxf(acc[n] + b3[n], 0.f);
    }
}

// ---------------- launch ----------------
// big: CTA 128x96, 192 thr, frag double-buffer; smem 3*(16K+12K)=84KB, 2 CTAs/SM
// small: CTA 128x128, 256 thr, single-buffer;   smem 3*32KB=96KB, 2 CTAs/SM
#define SMEM_BIG   (3 * (128 * 128 + 96 * 128))
#define SMEM_SMALL (3 * (128 * 128 + 128 * 128))

extern "C" void kernel_launch(void* const* d_in, const int* in_sizes, int n_in,
                              void* d_out, int out_size)
{
    const float* x        = (const float*)d_in[0];
    const float* gpe_mask = (const float*)d_in[1];
    const float* gpe_w    = (const float*)d_in[2];
    const float* gpe_b    = (const float*)d_in[3];
    const float* gpi_mask = (const float*)d_in[4];
    const float* gpi_w    = (const float*)d_in[5];
    const float* gpi_b    = (const float*)d_in[6];
    const float* w1       = (const float*)d_in[7];
    const float* b1       = (const float*)d_in[8];
    const float* w2       = (const float*)d_in[9];
    const float* b2       = (const float*)d_in[10];
    const float* w3       = (const float*)d_in[11];
    const float* b3       = (const float*)d_in[12];
    float* out = (float*)d_out;

    h16* s = nullptr;
    cudaGetSymbolAddress((void**)&s, g_scratch);

    h16 *xc = s + O_X;
    h16 *ge = s + O_GE, *gi = s + O_GI;
    h16 *h1 = s + O_H1, *h2 = s + O_H2;
    h16 *wge = s + O_WGE, *wgi = s + O_WGI;
    h16 *w1c = s + O_W1, *w2c = s + O_W2;

    auto kBig1 = gemm_hmma<128, 96, 192, true, false, false>;
    auto kBig2 = gemm_hmma<128, 96, 192, true, false, true>;
    auto kSm   = gemm_hmma<128, 128, 256, false, true, false>;

    cudaFuncSetAttribute(kBig1, cudaFuncAttributeMaxDynamicSharedMemorySize, SMEM_BIG);
    cudaFuncSetAttribute(kBig2, cudaFuncAttributeMaxDynamicSharedMemorySize, SMEM_BIG);
    cudaFuncSetAttribute(kSm,   cudaFuncAttributeMaxDynamicSharedMemorySize, SMEM_SMALL);

    // Launch order keeps the ncu window (slots ~4-6) on big GEMMs.
    cvt_kernel4<<<4096, 256>>>((const float4*)x, (__half2*)xc, SZ_X / 4);
    prep_T<true><<<dim3(D1 / 32, D1 / 32), dim3(32, 8)>>>(gpe_w, gpe_mask, wge, D1, D1);
    prep_T<true><<<dim3(D2 / 32, D1 / 32), dim3(32, 8)>>>(gpi_w, gpi_mask, wgi, D2, D1);
    // layer 1: gpe = x @ Wgpe + b        [B,1536] x [1536,1536]
    kBig1<<<dim3(D1 / 96, BDIM / 128), 192, SMEM_BIG>>>(
        xc, nullptr, D1, wge, gpe_b, ge, D1, D1);
    // layer 2: gpi = [x, gpe] @ Wgpi + b [B,3072] x [3072,1536] (concat fused)
    kBig2<<<dim3(D1 / 96, BDIM / 128), 192, SMEM_BIG>>>(
        xc, ge, D1, wgi, gpi_b, gi, D1, D2);
    prep_T<false><<<dim3(D1 / 32, DH / 32), dim3(32, 8)>>>(w1, nullptr, w1c, D1, DH);
    prep_T<false><<<dim3(DH / 32, DH / 32), dim3(32, 8)>>>(w2, nullptr, w2c, DH, DH);
    // layer 3: h1 = relu(gpi @ w1 + b1)  [B,1536] x [1536,512]
    kSm<<<dim3(DH / 128, BDIM / 128), 256, SMEM_SMALL>>>(
        gi, nullptr, D1, w1c, b1, h1, DH, D1);
    // layer 4: h2 = relu(h1 @ w2 + b2)   [B,512] x [512,512]
    kSm<<<dim3(DH / 128, BDIM / 128), 256, SMEM_SMALL>>>(
        h1, nullptr, DH, w2c, b2, h2, DH, DH);
    // layer 5: out = relu(h2 @ w3 + b3)  [B,512] x [512,6]
    final_kernel<<<(BDIM * 32) / 256, 256>>>(h2, w3, b3, out);
}

// round 15
// speedup vs baseline: 1.0155x; 1.0155x over previous
#include <cuda_runtime.h>
#include <cuda_fp16.h>
#include <cstdint>
#include <cstddef>

typedef __half h16;

#define BDIM 16384
#define D1   1536
#define D2   3072
#define DH   512
#define DOUT 6

// ---------------- scratch (static device memory; no allocations) ----------------
static constexpr size_t SZ_X   = (size_t)BDIM * D1;
static constexpr size_t SZ_H   = (size_t)BDIM * DH;
static constexpr size_t SZ_WGE = (size_t)D1 * D1;
static constexpr size_t SZ_WGI = (size_t)D2 * D1;
static constexpr size_t SZ_W1  = (size_t)D1 * DH;
static constexpr size_t SZ_W2  = (size_t)DH * DH;

static constexpr size_t O_X   = 0;
static constexpr size_t O_GE  = O_X  + SZ_X;
static constexpr size_t O_GI  = O_GE + SZ_X;
static constexpr size_t O_H1  = O_GI + SZ_X;
static constexpr size_t O_H2  = O_H1 + SZ_H;
static constexpr size_t O_WGE = O_H2 + SZ_H;
static constexpr size_t O_WGI = O_WGE + SZ_WGE;
static constexpr size_t O_W1  = O_WGI + SZ_WGI;
static constexpr size_t O_W2  = O_W1 + SZ_W1;
static constexpr size_t SCRATCH_TOTAL = O_W2 + SZ_W2;

__device__ __align__(1024) h16 g_scratch[SCRATCH_TOTAL];

// ---------------- ptx helpers ----------------
__device__ __forceinline__ uint32_t smem_u32(const void* p) {
    uint32_t a;
    asm("{ .reg .u64 t; cvta.to.shared.u64 t, %1; cvt.u32.u64 %0, t; }" : "=r"(a) : "l"(p));
    return a;
}

__device__ __forceinline__ void cp16(uint32_t dst, const void* src) {
    asm volatile("cp.async.cg.shared.global [%0], [%1], 16;" :: "r"(dst), "l"(src) : "memory");
}

__device__ __forceinline__ void ldmx4(uint32_t* r, uint32_t addr) {
    asm volatile("ldmatrix.sync.aligned.m8n8.x4.shared.b16 {%0,%1,%2,%3}, [%4];"
        : "=r"(r[0]), "=r"(r[1]), "=r"(r[2]), "=r"(r[3]) : "r"(addr));
}

__device__ __forceinline__ void mma16816(float* c, const uint32_t* a, const uint32_t* b) {
    asm volatile(
        "mma.sync.aligned.m16n8k16.row.col.f32.f16.f16.f32 "
        "{%0,%1,%2,%3},{%4,%5,%6,%7},{%8,%9},{%0,%1,%2,%3};\n"
        : "+f"(c[0]), "+f"(c[1]), "+f"(c[2]), "+f"(c[3])
        : "r"(a[0]), "r"(a[1]), "r"(a[2]), "r"(a[3]),
          "r"(b[0]), "r"(b[1]));
}

// ---------------- prep kernels ----------------
__global__ void cvt_kernel4(const float4* __restrict__ src,
                            __half2* __restrict__ dst, size_t n4) {
    size_t stride = (size_t)gridDim.x * blockDim.x;
    for (size_t i = (size_t)blockIdx.x * blockDim.x + threadIdx.x; i < n4; i += stride) {
        float4 v = src[i];
        dst[2 * i]     = __floats2half2_rn(v.x, v.y);
        dst[2 * i + 1] = __floats2half2_rn(v.z, v.w);
    }
}

template<bool MASKED>
__global__ void prep_T(const float* __restrict__ w, const float* __restrict__ mask,
                       h16* __restrict__ t, int Kd, int Nd) {
    __shared__ float tl[32][33];
    const int k0 = blockIdx.x * 32, n0 = blockIdx.y * 32;
    const int tx = threadIdx.x, ty = threadIdx.y;  // 32 x 8
#pragma unroll
    for (int i = 0; i < 32; i += 8)
        tl[ty + i][tx] = w[(size_t)(k0 + ty + i) * Nd + (n0 + tx)];
    __syncthreads();
#pragma unroll
    for (int i = 0; i < 32; i += 8) {
        const int n = n0 + ty + i, k = k0 + tx;
        float v = tl[tx][ty + i];
        const size_t idx = (size_t)n * Kd + k;
        if (MASKED) v *= mask[idx];
        t[idx] = __float2half_rn(v);
    }
}

// ---------------- mma.sync GEMM: C = A * B^T(+concat) + bias (opt relu), fp16 ----------------
// BK=64 (128B swizzled rows), 3-stage cp.async (1 barrier/stage), 2 CTAs/SM.
// Big config:   CTA 128x128, 128 thr (4 warps), warp tile 64x64 -> 8 ldmx4 per 32 MMA
//               (smem port per MMA drops 192B->128B read; under port budget).
// Small config: CTA 128x128, 256 thr (8 warps), warp tile 64x32 (proven R11 shape).
template<int CBM, int CBN, int THREADS, int WM, int WN, bool RELU, bool CONCAT>
__global__ __launch_bounds__(THREADS, 2)
void gemm_hmma(const h16* __restrict__ A, const h16* __restrict__ A2,
               int ksplit,
               const h16* __restrict__ Bt,  // [N][K]
               const float* __restrict__ bias,
               h16* __restrict__ O,
               int N, int K)
{
    constexpr int WARPS_N = CBN / WN;
    constexpr int NI  = WM / 16;
    constexpr int NJ  = WN / 8;
    constexpr int NJP = WN / 16;
    constexpr int ABYTES = CBM * 128;
    constexpr int BBYTES = CBN * 128;
    constexpr int STAGEB = ABYTES + BBYTES;
    constexpr int ACH = CBM * 8;
    constexpr int BCH = CBN * 8;

    extern __shared__ __align__(1024) char smem[];
    const uint32_t sb = smem_u32(smem);

    const int tid  = threadIdx.x;
    const int lane = tid & 31;
    const int warp = tid >> 5;
    const int wm = warp / WARPS_N;
    const int wn = warp % WARPS_N;
    const int blockN = blockIdx.x * CBN;
    const int blockM = blockIdx.y * CBM;

    // ldmatrix lane decomposition
    const int q = lane >> 3;
    const int m8 = lane & 7;
    const int qrA = q & 1;
    const int qcA = q >> 1;
    const int qrB = q >> 1;
    const int qcB = q & 1;

    uint32_t rA[NI], xA[NI];
#pragma unroll
    for (int i = 0; i < NI; i++) {
        int row = wm * WM + i * 16 + qrA * 8 + m8;
        rA[i] = (uint32_t)row * 128u;
        xA[i] = (uint32_t)(row & 7);
    }
    uint32_t rB[NJP], xB[NJP];
#pragma unroll
    for (int jp = 0; jp < NJP; jp++) {
        int row = wn * WN + jp * 16 + qrB * 8 + m8;
        rB[jp] = (uint32_t)row * 128u;
        xB[jp] = (uint32_t)(row & 7);
    }

    float acc[NI][NJ][4];
#pragma unroll
    for (int i = 0; i < NI; i++)
#pragma unroll
        for (int j = 0; j < NJ; j++)
#pragma unroll
            for (int r = 0; r < 4; r++) acc[i][j][r] = 0.f;

    const int S = K / 64;

    auto do_load = [&](int s) {
        const int k0 = s * 64;
        const h16* a;
        size_t lda;
        if (CONCAT && k0 >= ksplit) {
            lda = (size_t)(K - ksplit);
            a = A2 + (size_t)blockM * lda + (k0 - ksplit);
        } else {
            lda = CONCAT ? (size_t)ksplit : (size_t)K;
            a = A + (size_t)blockM * lda + k0;
        }
        const h16* b = Bt + (size_t)blockN * K + k0;
        const uint32_t buf = sb + (uint32_t)(s % 3) * STAGEB;
#pragma unroll 1
        for (int c = tid; c < ACH; c += THREADS) {
            const int row = c >> 3;
            const int col = c & 7;
            const uint32_t soff = (uint32_t)row * 128u + (uint32_t)((col ^ (row & 7)) * 16);
            cp16(buf + soff, (const char*)(a + (size_t)row * lda) + col * 16);
        }
#pragma unroll 1
        for (int c = tid; c < BCH; c += THREADS) {
            const int row = c >> 3;
            const int col = c & 7;
            const uint32_t soff = (uint32_t)row * 128u + (uint32_t)((col ^ (row & 7)) * 16);
            cp16(buf + ABYTES + soff, (const char*)(b + (size_t)row * K) + col * 16);
        }
    };

    do_load(0);
    asm volatile("cp.async.commit_group;" ::: "memory");
    if (S > 1) {
        do_load(1);
        asm volatile("cp.async.commit_group;" ::: "memory");
    }

    for (int s = 0; s < S; s++) {
        if (s < S - 1) asm volatile("cp.async.wait_group 1;" ::: "memory");
        else           asm volatile("cp.async.wait_group 0;" ::: "memory");
        __syncthreads();   // single barrier per stage (3-stage ring)

        if (s + 2 < S) {
            do_load(s + 2);
            asm volatile("cp.async.commit_group;" ::: "memory");
        }

        const uint32_t buf = sb + (uint32_t)(s % 3) * STAGEB;
        const uint32_t bA = buf;
        const uint32_t bB = buf + ABYTES;

#pragma unroll
        for (int ks = 0; ks < 4; ks++) {
            const uint32_t cA = (uint32_t)(ks * 2 + qcA);
            const uint32_t cB = (uint32_t)(ks * 2 + qcB);
            uint32_t af[NI][4], bf[NJP][4];
#pragma unroll
            for (int i = 0; i < NI; i++)
                ldmx4(af[i], bA + rA[i] + ((cA ^ xA[i]) << 4));
#pragma unroll
            for (int jp = 0; jp < NJP; jp++)
                ldmx4(bf[jp], bB + rB[jp] + ((cB ^ xB[jp]) << 4));
#pragma unroll
            for (int j = 0; j < NJ; j++)
#pragma unroll
                for (int i = 0; i < NI; i++)
                    mma16816(acc[i][j], af[i], &bf[j >> 1][(j & 1) * 2]);
        }
    }

    // ---- epilogue: bias, optional relu, fp16 store
    const int g  = lane >> 2;
    const int tg = lane & 3;
#pragma unroll
    for (int i = 0; i < NI; i++) {
#pragma unroll
        for (int j = 0; j < NJ; j++) {
            int row0 = blockM + wm * WM + i * 16 + g;
            int col  = blockN + wn * WN + j * 8 + tg * 2;
            float b0 = bias[col], b1 = bias[col + 1];
#pragma unroll
            for (int h = 0; h < 2; h++) {
                int row = row0 + h * 8;
                float v0 = acc[i][j][h * 2 + 0] + b0;
                float v1 = acc[i][j][h * 2 + 1] + b1;
                if (RELU) { v0 = fmaxf(v0, 0.f); v1 = fmaxf(v1, 0.f); }
                *(__half2*)&O[(size_t)row * N + col] = __floats2half2_rn(v0, v1);
            }
        }
    }
}

// ---------------- final layer: [B,512] x [512,6] + bias, relu (fp32) ----------------
__global__ void final_kernel(const h16* __restrict__ hh,
                             const float* __restrict__ w3, const float* __restrict__ b3,
                             float* __restrict__ out)
{
    int warpId = (int)((blockIdx.x * (size_t)blockDim.x + threadIdx.x) >> 5);
    int lane = threadIdx.x & 31;
    if (warpId >= BDIM) return;
    const h16* ph = hh + (size_t)warpId * DH;
    float acc[6] = {0.f, 0.f, 0.f, 0.f, 0.f, 0.f};
    for (int k = lane; k < DH; k += 32) {
        float h = __half2float(ph[k]);
#pragma unroll
        for (int n = 0; n < 6; n++) acc[n] += h * w3[k * 6 + n];
    }
#pragma unroll
    for (int n = 0; n < 6; n++)
#pragma unroll
        for (int off = 16; off; off >>= 1)
            acc[n] += __shfl_xor_sync(0xffffffffu, acc[n], off);
    if (lane == 0) {
#pragma unroll
        for (int n = 0; n < 6; n++)
            out[(size_t)warpId * 6 + n] = fmaxf(acc[n] + b3[n], 0.f);
    }
}

// ---------------- launch ----------------
// big: CTA 128x128, 128 thr, warp 64x64; smem 3*32KB=96KB, 2 CTAs/SM, 256-reg cap
// small: CTA 128x128, 256 thr, warp 64x32; same smem, proven R11 shape
#define SMEM_TILE (3 * (128 * 128 + 128 * 128))

extern "C" void kernel_launch(void* const* d_in, const int* in_sizes, int n_in,
                              void* d_out, int out_size)
{
    const float* x        = (const float*)d_in[0];
    const float* gpe_mask = (const float*)d_in[1];
    const float* gpe_w    = (const float*)d_in[2];
    const float* gpe_b    = (const float*)d_in[3];
    const float* gpi_mask = (const float*)d_in[4];
    const float* gpi_w    = (const float*)d_in[5];
    const float* gpi_b    = (const float*)d_in[6];
    const float* w1       = (const float*)d_in[7];
    const float* b1       = (const float*)d_in[8];
    const float* w2       = (const float*)d_in[9];
    const float* b2       = (const float*)d_in[10];
    const float* w3       = (const float*)d_in[11];
    const float* b3       = (const float*)d_in[12];
    float* out = (float*)d_out;

    h16* s = nullptr;
    cudaGetSymbolAddress((void**)&s, g_scratch);

    h16 *xc = s + O_X;
    h16 *ge = s + O_GE, *gi = s + O_GI;
    h16 *h1 = s + O_H1, *h2 = s + O_H2;
    h16 *wge = s + O_WGE, *wgi = s + O_WGI;
    h16 *w1c = s + O_W1, *w2c = s + O_W2;

    auto kBig1 = gemm_hmma<128, 128, 128, 64, 64, false, false>;
    auto kBig2 = gemm_hmma<128, 128, 128, 64, 64, false, true>;
    auto kSm   = gemm_hmma<128, 128, 256, 64, 32, true, false>;

    cudaFuncSetAttribute(kBig1, cudaFuncAttributeMaxDynamicSharedMemorySize, SMEM_TILE);
    cudaFuncSetAttribute(kBig2, cudaFuncAttributeMaxDynamicSharedMemorySize, SMEM_TILE);
    cudaFuncSetAttribute(kSm,   cudaFuncAttributeMaxDynamicSharedMemorySize, SMEM_TILE);

    // Launch order keeps the ncu window (slots ~4-6) on big GEMMs.
    cvt_kernel4<<<4096, 256>>>((const float4*)x, (__half2*)xc, SZ_X / 4);
    prep_T<true><<<dim3(D1 / 32, D1 / 32), dim3(32, 8)>>>(gpe_w, gpe_mask, wge, D1, D1);
    prep_T<true><<<dim3(D2 / 32, D1 / 32), dim3(32, 8)>>>(gpi_w, gpi_mask, wgi, D2, D1);
    // layer 1: gpe = x @ Wgpe + b        [B,1536] x [1536,1536]
    kBig1<<<dim3(D1 / 128, BDIM / 128), 128, SMEM_TILE>>>(
        xc, nullptr, D1, wge, gpe_b, ge, D1, D1);
    // layer 2: gpi = [x, gpe] @ Wgpi + b [B,3072] x [3072,1536] (concat fused)
    kBig2<<<dim3(D1 / 128, BDIM / 128), 128, SMEM_TILE>>>(
        xc, ge, D1, wgi, gpi_b, gi, D1, D2);
    prep_T<false><<<dim3(D1 / 32, DH / 32), dim3(32, 8)>>>(w1, nullptr, w1c, D1, DH);
    prep_T<false><<<dim3(DH / 32, DH / 32), dim3(32, 8)>>>(w2, nullptr, w2c, DH, DH);
    // layer 3: h1 = relu(gpi @ w1 + b1)  [B,1536] x [1536,512]
    kSm<<<dim3(DH / 128, BDIM / 128), 256, SMEM_TILE>>>(
        gi, nullptr, D1, w1c, b1, h1, DH, D1);
    // layer 4: h2 = relu(h1 @ w2 + b2)   [B,512] x [512,512]
    kSm<<<dim3(DH / 128, BDIM / 128), 256, SMEM_TILE>>>(
        h1, nullptr, DH, w2c, b2, h2, DH, DH);
    // layer 5: out = relu(h2 @ w3 + b3)  [B,512] x [512,6]
    final_kernel<<<(BDIM * 32) / 256, 256>>>(h2, w3, b3, out);
}